// round 1
// baseline (speedup 1.0000x reference)
#include <cuda_runtime.h>

// Polyphase upsample-by-2 + 10001-tap FIR (full conv), fp32.
// out[b, 2p]   = sum_q w[2q]   * x[b, p-q],  q in [0,5000]
// out[b, 2p+1] = sum_q w[2q+1] * x[b, p-q],  q in [0,4999]
// Both phases share x reads; tap pairs (w[2q], w[2q+1]) are contiguous in w,
// so we accumulate both with one packed fma.rn.f32x2 per (r, q).

#define TNUM 256
#define RPT  8
#define TILE_P (TNUM * RPT)     // 2048 p-positions per block
#define NQ   5008               // taps per phase padded to multiple of 8
#define PAD  NQ
#define LEN  262144             // L
#define QLEN 10001              // filter length
#define NPAIR 267144            // number of (even,odd) output pairs per row = L + (Q-1)/2
#define OUTW 534288             // output row length = 2*NPAIR

#define XS_ELEMS (TILE_P + PAD)       // 7056 floats
#define WS_ELEMS (2 * NQ)             // 10016 floats (interleaved pairs, zero padded)
#define SMEM_BYTES ((XS_ELEMS + WS_ELEMS) * 4)   // 68288 bytes

__global__ __launch_bounds__(TNUM) void upfir2_kernel(
    const float* __restrict__ x,
    const float* __restrict__ w,
    float* __restrict__ out)
{
    extern __shared__ float sm[];
    float* xs = sm;              // x tile: xs[j] = x[p0 - PAD + j]
    float* ws = sm + XS_ELEMS;   // tap pairs, zero-padded

    const int t  = threadIdx.x;
    const int p0 = blockIdx.x * TILE_P;
    const int b  = blockIdx.y;
    const float* xb = x + (size_t)b * LEN;

    // Stage x tile (zero-pad out-of-range)
    for (int j = t; j < XS_ELEMS; j += TNUM) {
        int g = p0 - PAD + j;
        xs[j] = (g >= 0 && g < LEN) ? __ldg(xb + g) : 0.0f;
    }
    // Stage filter taps (interleaved pairs as-is), zero pad to 2*NQ
    for (int j = t; j < WS_ELEMS; j += TNUM) {
        ws[j] = (j < QLEN) ? __ldg(w + j) : 0.0f;
    }
    __syncthreads();

    // Packed accumulators: low lane = even phase, high lane = odd phase
    unsigned long long acc[RPT];
    unsigned long long xx[RPT];   // duplicated x value in both lanes
#pragma unroll
    for (int r = 0; r < RPT; ++r) acc[r] = 0ull;

    const int lb = t * RPT + PAD;   // local index of x[pt] in xs
#pragma unroll
    for (int r = 0; r < RPT; ++r) {
        float v = xs[lb + r];
        asm("mov.b64 %0, {%1, %1};" : "=l"(xx[r]) : "f"(v));
    }

    const unsigned long long* wsp =
        reinterpret_cast<const unsigned long long*>(ws);

#pragma unroll 2
    for (int q0 = 0; q0 < NQ; q0 += 4) {
        // next 4 sliding-window entries, descending use: xs[lb-q0-4 .. lb-q0-1]
        float4 xn = *reinterpret_cast<const float4*>(xs + lb - q0 - 4);
        float nx0 = xn.w, nx1 = xn.z, nx2 = xn.y, nx3 = xn.x;
#pragma unroll
        for (int u = 0; u < 4; ++u) {
            unsigned long long wq = wsp[q0 + u];   // (w[2q], w[2q+1]) broadcast
#pragma unroll
            for (int r = 0; r < RPT; ++r)
                asm("fma.rn.f32x2 %0, %1, %2, %0;"
                    : "+l"(acc[r]) : "l"(wq), "l"(xx[r]));
            // slide window: xx[r] <- xx[r-1]; xx[0] <- x[pt - (q+1)]
#pragma unroll
            for (int r = RPT - 1; r >= 1; --r) xx[r] = xx[r - 1];
            float nv = (u == 0) ? nx0 : (u == 1) ? nx1 : (u == 2) ? nx2 : nx3;
            asm("mov.b64 %0, {%1, %1};" : "=l"(xx[0]) : "f"(nv));
        }
    }

    // Store: acc[r] low = out[2p], high = out[2p+1] -> one float2
    float2* ob = reinterpret_cast<float2*>(out + (size_t)b * OUTW);
    const int pt = p0 + t * RPT;
#pragma unroll
    for (int r = 0; r < RPT; ++r) {
        int p = pt + r;
        if (p < NPAIR) ob[p] = *reinterpret_cast<float2*>(&acc[r]);
    }
}

extern "C" void kernel_launch(void* const* d_in, const int* in_sizes, int n_in,
                              void* d_out, int out_size)
{
    const float* x = (const float*)d_in[0];
    const float* w = (const float*)d_in[1];
    float* out = (float*)d_out;

    cudaFuncSetAttribute(upfir2_kernel,
                         cudaFuncAttributeMaxDynamicSharedMemorySize,
                         SMEM_BYTES);

    dim3 grid((NPAIR + TILE_P - 1) / TILE_P, 32);   // (131, 32)
    upfir2_kernel<<<grid, TNUM, SMEM_BYTES>>>(x, w, out);
}